// round 10
// baseline (speedup 1.0000x reference)
#include <cuda_runtime.h>

// RiRoIAlign for GB300 — full tap-parallel warp layout (16 lanes per bin).
// features: (B=2, Ctot=256, H=256, W=256) fp32
// rois: (512, 6) fp32 = [batch, cx, cy, w, h, theta]
// out: (512, 256, 7, 7) fp32, channel = c*8 + o  (C=32, O=8)
//
// grid = (512 rois, 16 channel pairs). Warp = 2 consecutive (plane,bin) items;
// lane = (item(1b), sample(2b), ytap(1b), xside(1b)). Each lane loads ONE tap
// per channel (scalar LDG.32) with its fully-folded bilinear weight; the bin
// value is a 16-lane shfl reduction. One LDG instruction covers all 16 taps
// of 4 samples x 2 adjacent bins -> max line dedup per L1 wavefront.

#define HH 256
#define WW 256
#define CT 256
#define OO 8
#define NBIN 49
#define NS 196
#define HW (HH * WW)
#define NITEM (OO * NBIN)        // 392
#define NOUT (2 * NITEM)         // 784

__global__ __launch_bounds__(256, 6)
void riroi_kernel(const float* __restrict__ features,
                  const float* __restrict__ rois,
                  float* __restrict__ out)
{
    __shared__ int4   soff[NS];   // taps: (yl,xl),(yl,xh),(yh,xl),(yh,xh) offsets
    __shared__ float4 swt[NS];    // folded weights: w00,w01,w10,w11 (incl. vm)
    __shared__ float  acc[NOUT];

    const int r   = blockIdx.x;
    const int cg  = blockIdx.y;          // 16 channel pairs
    const int tid = threadIdx.x;

    const float b_f = rois[r * 6 + 0];
    const float cwv = rois[r * 6 + 1] * 0.125f;
    const float chv = rois[r * 6 + 2] * 0.125f;
    const float rw  = fmaxf(rois[r * 6 + 3] * 0.125f, 1.0f);
    const float rh  = fmaxf(rois[r * 6 + 4] * 0.125f, 1.0f);
    const float th  = rois[r * 6 + 5];
    const int   b   = (int)b_f;

    const float st  = sinf(th);
    const float ctt = cosf(th);

    const float indf   = (th * 8.0f) / 6.283185307179586f;
    const float indflo = floorf(indf);
    const float lv     = indf - indflo;
    const float rv     = 1.0f - lv;
    int ind = (int)indflo;
    ind = ((ind % 8) + 8) % 8;

    const float bin_h = rh / 7.0f;
    const float bin_w = rw / 7.0f;

    // ---- geometry, bin-major: s = bin*4 + (gy*2+gx) ----
    if (tid < NS) {
        const int s   = tid;
        const int gx  = s & 1;
        const int gy  = (s >> 1) & 1;
        const int bin = s >> 2;
        const int py  = bin / 7;
        const int px  = bin - py * 7;

        const float yy = -rh * 0.5f + ((float)py + ((float)gy + 0.5f) * 0.5f) * bin_h;
        const float xx = -rw * 0.5f + ((float)px + ((float)gx + 0.5f) * 0.5f) * bin_w;

        const float x = xx * ctt - yy * st + cwv;
        const float y = xx * st + yy * ctt + chv;

        const bool valid = (y > -1.0f) && (y < 256.0f) && (x > -1.0f) && (x < 256.0f);

        const float yc = fmaxf(y, 0.0f);
        const float xc = fmaxf(x, 0.0f);
        int yl = (int)yc;
        int xl = (int)xc;
        int yh, xh;
        float yv, xv;
        if (yl >= HH - 1) { yl = HH - 1; yh = HH - 1; yv = (float)(HH - 1); }
        else              { yh = yl + 1;              yv = yc; }
        if (xl >= WW - 1) { xl = WW - 1; xh = WW - 1; xv = (float)(WW - 1); }
        else              { xh = xl + 1;              xv = xc; }

        const float ly = yv - (float)yl;
        const float lx = xv - (float)xl;
        const float hy = 1.0f - ly;
        const float hx = 1.0f - lx;
        const float vm = valid ? 1.0f : 0.0f;

        swt[s]  = make_float4(hy * hx * vm, hy * lx * vm, ly * hx * vm, ly * lx * vm);
        soff[s] = make_int4(yl * WW + xl, yl * WW + xh, yh * WW + xl, yh * WW + xh);
    }
    __syncthreads();

    // base: features[b, cg*16 + {0,1}*8 + plane, :, :]
    const float* fbase = features + ((size_t)b * CT + (size_t)cg * 16) * (size_t)HW;

    const int warp = tid >> 5;
    const int lane = tid & 31;
    const int isub = lane >> 4;          // item within warp's pair
    const int q    = (lane >> 2) & 3;    // sample within bin
    const int t    = lane & 3;           // tap: 0=(yl,xl) 1=(yl,xh) 2=(yh,xl) 3=(yh,xh)

    // warp covers items {gBase, gBase+1}; 8 warps -> stride 16 items per pass.
    // NITEM=392 is even, so both items of an active warp are always valid.
    for (int gBase = warp * 2; gBase < NITEM; gBase += 16) {
        const int g     = gBase + isub;
        const int plane = g / NBIN;
        const int bin   = g - plane * NBIN;
        const int s     = bin * 4 + q;

        const int   off = ((const int*)&soff[s])[t];
        const float wgt = ((const float*)&swt[s])[t];

        const float* p0 = fbase + plane * HW;
        const float* p1 = p0 + OO * HW;

        float v0 = wgt * __ldg(p0 + off);
        float v1 = wgt * __ldg(p1 + off);

        // sum the 16 lanes (4 samples x 4 taps) of this bin
        v0 += __shfl_xor_sync(0xFFFFFFFFu, v0, 1);
        v1 += __shfl_xor_sync(0xFFFFFFFFu, v1, 1);
        v0 += __shfl_xor_sync(0xFFFFFFFFu, v0, 2);
        v1 += __shfl_xor_sync(0xFFFFFFFFu, v1, 2);
        v0 += __shfl_xor_sync(0xFFFFFFFFu, v0, 4);
        v1 += __shfl_xor_sync(0xFFFFFFFFu, v1, 4);
        v0 += __shfl_xor_sync(0xFFFFFFFFu, v0, 8);
        v1 += __shfl_xor_sync(0xFFFFFFFFu, v1, 8);

        if ((lane & 15) == 0) {
            acc[g]         = v0;
            acc[NITEM + g] = v1;
        }
    }
    __syncthreads();

    // out[r, cg*16 .. +16, 7, 7]: contiguous 784 floats; j = cc*392 + o*49 + bin.
    float* ob = out + ((size_t)r * CT + (size_t)cg * 16) * (size_t)NBIN;
    #pragma unroll
    for (int jj = 0; jj < 4; ++jj) {
        const int j = jj * 256 + tid;
        if (j < NOUT) {
            const int cc   = j / NITEM;
            const int rest = j - cc * NITEM;
            const int o    = rest / NBIN;
            const int bin  = rest - o * NBIN;
            const int p0i  = (o - ind + 8) & 7;
            const int p1i  = (p0i + 1) & 7;
            ob[j] = 0.25f * (rv * acc[cc * NITEM + p0i * NBIN + bin]
                           + lv * acc[cc * NITEM + p1i * NBIN + bin]);
        }
    }
}

extern "C" void kernel_launch(void* const* d_in, const int* in_sizes, int n_in,
                              void* d_out, int out_size)
{
    const float* features = (const float*)d_in[0];
    const float* rois     = (const float*)d_in[1];
    float*       out      = (float*)d_out;

    const int R = in_sizes[1] / 6;
    dim3 grid((unsigned)R, 16);
    riroi_kernel<<<grid, 256>>>(features, rois, out);
}

// round 11
// speedup vs baseline: 1.2412x; 1.2412x over previous
#include <cuda_runtime.h>

// RiRoIAlign for GB300 — R9 tap-parallel layout + fused geometry table.
// features: (B=2, Ctot=256, H=256, W=256) fp32
// rois: (512, 6) fp32 = [batch, cx, cy, w, h, theta]
// out: (512, 256, 7, 7) fp32, channel = c*8 + o  (C=32, O=8)
//
// grid = (512 rois, 16 channel pairs). Warp = 4 consecutive (plane,bin) items;
// lane = (item(2b), sample(2b), x-side(1b)). Geometry is pre-fused per
// (sample, x-side) into ONE float4 {offL, offH, wx*hy*vm, wx*ly*vm}
// (offsets bit-cast) so the hot loop does 1 LDS.128 + 2 LDG.32/channel +
// 2 FFMA/channel, then an 8-lane shfl reduction per bin.

#define HH 256
#define WW 256
#define CT 256
#define OO 8
#define NBIN 49
#define NS 196
#define HW (HH * WW)
#define NITEM (OO * NBIN)        // 392
#define NOUT (2 * NITEM)         // 784

__global__ __launch_bounds__(256, 6)
void riroi_kernel(const float* __restrict__ features,
                  const float* __restrict__ rois,
                  float* __restrict__ out)
{
    __shared__ float4 sgeo[NS * 2];   // [s*2+side] = {offL(i), offH(i), wHY, wLY}
    __shared__ float  acc[NOUT];

    const int r   = blockIdx.x;
    const int cg  = blockIdx.y;          // 16 channel pairs
    const int tid = threadIdx.x;

    const float b_f = rois[r * 6 + 0];
    const float cwv = rois[r * 6 + 1] * 0.125f;
    const float chv = rois[r * 6 + 2] * 0.125f;
    const float rw  = fmaxf(rois[r * 6 + 3] * 0.125f, 1.0f);
    const float rh  = fmaxf(rois[r * 6 + 4] * 0.125f, 1.0f);
    const float th  = rois[r * 6 + 5];
    const int   b   = (int)b_f;

    const float st  = sinf(th);
    const float ctt = cosf(th);

    const float indf   = (th * 8.0f) / 6.283185307179586f;
    const float indflo = floorf(indf);
    const float lv     = indf - indflo;
    const float rv     = 1.0f - lv;
    int ind = (int)indflo;
    ind = ((ind % 8) + 8) % 8;

    const float bin_h = rh / 7.0f;
    const float bin_w = rw / 7.0f;

    // ---- geometry, bin-major: s = bin*4 + (gy*2+gx) ----
    if (tid < NS) {
        const int s   = tid;
        const int gx  = s & 1;
        const int gy  = (s >> 1) & 1;
        const int bin = s >> 2;
        const int py  = bin / 7;
        const int px  = bin - py * 7;

        const float yy = -rh * 0.5f + ((float)py + ((float)gy + 0.5f) * 0.5f) * bin_h;
        const float xx = -rw * 0.5f + ((float)px + ((float)gx + 0.5f) * 0.5f) * bin_w;

        const float x = xx * ctt - yy * st + cwv;
        const float y = xx * st + yy * ctt + chv;

        const bool valid = (y > -1.0f) && (y < 256.0f) && (x > -1.0f) && (x < 256.0f);

        const float yc = fmaxf(y, 0.0f);
        const float xc = fmaxf(x, 0.0f);
        int yl = (int)yc;
        int xl = (int)xc;
        int yh, xh;
        float yv, xv;
        if (yl >= HH - 1) { yl = HH - 1; yh = HH - 1; yv = (float)(HH - 1); }
        else              { yh = yl + 1;              yv = yc; }
        if (xl >= WW - 1) { xl = WW - 1; xh = WW - 1; xv = (float)(WW - 1); }
        else              { xh = xl + 1;              xv = xc; }

        const float ly = yv - (float)yl;
        const float lx = xv - (float)xl;
        const float hy = (1.0f - ly) * (valid ? 1.0f : 0.0f);
        const float hyv = hy;
        const float lyv = ly * (valid ? 1.0f : 0.0f);
        const float hx = 1.0f - lx;

        const int rowL = yl * WW;
        const int rowH = yh * WW;

        // side 0: x = xl, wx = hx ; side 1: x = xh, wx = lx
        sgeo[2 * s + 0] = make_float4(__int_as_float(rowL + xl),
                                      __int_as_float(rowH + xl),
                                      hx * hyv, hx * lyv);
        sgeo[2 * s + 1] = make_float4(__int_as_float(rowL + xh),
                                      __int_as_float(rowH + xh),
                                      lx * hyv, lx * lyv);
    }
    __syncthreads();

    // base: features[b, cg*16 + {0,1}*8 + plane, :, :]
    const float* fbase = features + ((size_t)b * CT + (size_t)cg * 16) * (size_t)HW;

    const int warp = tid >> 5;
    const int lane = tid & 31;
    const int isub = lane >> 3;          // item within warp's group of 4
    const int sub8 = lane & 7;           // (sample(2b), side(1b)) within bin

    for (int gBase = warp * 4; gBase < NITEM; gBase += 32) {
        const int g     = gBase + isub;
        const int plane = g / NBIN;
        const int bin   = g - plane * NBIN;

        const float4 gg = sgeo[bin * 8 + sub8];
        const int offL  = __float_as_int(gg.x);
        const int offH  = __float_as_int(gg.y);

        const float* p0 = fbase + plane * HW;
        const float* p1 = p0 + OO * HW;

        const float t0L = __ldg(p0 + offL);
        const float t0H = __ldg(p0 + offH);
        const float t1L = __ldg(p1 + offL);
        const float t1H = __ldg(p1 + offH);

        float v0 = gg.z * t0L + gg.w * t0H;
        float v1 = gg.z * t1L + gg.w * t1H;

        // sum the 8 lanes (4 samples x 2 sides) of this bin
        v0 += __shfl_xor_sync(0xFFFFFFFFu, v0, 1);
        v1 += __shfl_xor_sync(0xFFFFFFFFu, v1, 1);
        v0 += __shfl_xor_sync(0xFFFFFFFFu, v0, 2);
        v1 += __shfl_xor_sync(0xFFFFFFFFu, v1, 2);
        v0 += __shfl_xor_sync(0xFFFFFFFFu, v0, 4);
        v1 += __shfl_xor_sync(0xFFFFFFFFu, v1, 4);

        if (sub8 == 0) {
            acc[g]         = v0;
            acc[NITEM + g] = v1;
        }
    }
    __syncthreads();

    // out[r, cg*16 .. +16, 7, 7]: contiguous 784 floats; j = cc*392 + o*49 + bin.
    float* ob = out + ((size_t)r * CT + (size_t)cg * 16) * (size_t)NBIN;
    #pragma unroll
    for (int jj = 0; jj < 4; ++jj) {
        const int j = jj * 256 + tid;
        if (j < NOUT) {
            const int cc   = j / NITEM;
            const int rest = j - cc * NITEM;
            const int o    = rest / NBIN;
            const int bin  = rest - o * NBIN;
            const int p0i  = (o - ind + 8) & 7;
            const int p1i  = (p0i + 1) & 7;
            ob[j] = 0.25f * (rv * acc[cc * NITEM + p0i * NBIN + bin]
                           + lv * acc[cc * NITEM + p1i * NBIN + bin]);
        }
    }
}

extern "C" void kernel_launch(void* const* d_in, const int* in_sizes, int n_in,
                              void* d_out, int out_size)
{
    const float* features = (const float*)d_in[0];
    const float* rois     = (const float*)d_in[1];
    float*       out      = (float*)d_out;

    const int R = in_sizes[1] / 6;
    dim3 grid((unsigned)R, 16);
    riroi_kernel<<<grid, 256>>>(features, rois, out);
}

// round 12
// speedup vs baseline: 1.2679x; 1.0215x over previous
#include <cuda_runtime.h>

// RiRoIAlign for GB300 — tap-parallel gather + 2x2 bin grouping per warp-LDG.
// features: (B=2, Ctot=256, H=256, W=256) fp32
// rois: (512, 6) fp32 = [batch, cx, cy, w, h, theta]
// out: (512, 256, 7, 7) fp32, channel = c*8 + o  (C=32, O=8)
//
// grid = (512 rois, 16 channel pairs). Warp = 4 (plane,bin) items, 8 lanes per
// bin = (sample(2b), x-side(1b)); geometry fused into one float4 per
// (sample,side): {offL, offH, wx*hy*vm, wx*ly*vm}. The 4 bins of a warp pass
// are a 2x2 spatial tile (snake order over column pairs) to minimize the
// distinct 128B lines touched per LDG instruction for any ROI rotation.

#define HH 256
#define WW 256
#define CT 256
#define OO 8
#define NBIN 49
#define NS 196
#define HW (HH * WW)
#define NITEM (OO * NBIN)        // 392
#define NOUT (2 * NITEM)         // 784

// snake permutation: j -> bin, grouping consecutive 4 j's into 2x2 tiles.
// j in [0,42): column pair c=j/14, t=j%14, py=t>>1, px=2c+(t&1).
// j in [42,49): last column px=6, py=j-42 (vertical 4x1 groups).
__device__ __forceinline__ int bin_perm(int j) {
    if (j < 42) {
        const int c  = j / 14;
        const int t  = j - c * 14;
        return (t >> 1) * 7 + 2 * c + (t & 1);
    }
    return (j - 42) * 7 + 6;
}

__global__ __launch_bounds__(256, 6)
void riroi_kernel(const float* __restrict__ features,
                  const float* __restrict__ rois,
                  float* __restrict__ out)
{
    __shared__ float4 sgeo[NS * 2];   // [s*2+side] = {offL(i), offH(i), wHY, wLY}
    __shared__ float  acc[NOUT];

    const int r   = blockIdx.x;
    const int cg  = blockIdx.y;          // 16 channel pairs
    const int tid = threadIdx.x;

    const float b_f = rois[r * 6 + 0];
    const float cwv = rois[r * 6 + 1] * 0.125f;
    const float chv = rois[r * 6 + 2] * 0.125f;
    const float rw  = fmaxf(rois[r * 6 + 3] * 0.125f, 1.0f);
    const float rh  = fmaxf(rois[r * 6 + 4] * 0.125f, 1.0f);
    const float th  = rois[r * 6 + 5];
    const int   b   = (int)b_f;

    const float st  = sinf(th);
    const float ctt = cosf(th);

    const float indf   = (th * 8.0f) / 6.283185307179586f;
    const float indflo = floorf(indf);
    const float lv     = indf - indflo;
    const float rv     = 1.0f - lv;
    int ind = (int)indflo;
    ind = ((ind % 8) + 8) % 8;

    const float bin_h = rh / 7.0f;
    const float bin_w = rw / 7.0f;

    // ---- geometry, bin-major: s = bin*4 + (gy*2+gx) ----
    if (tid < NS) {
        const int s   = tid;
        const int gx  = s & 1;
        const int gy  = (s >> 1) & 1;
        const int bin = s >> 2;
        const int py  = bin / 7;
        const int px  = bin - py * 7;

        const float yy = -rh * 0.5f + ((float)py + ((float)gy + 0.5f) * 0.5f) * bin_h;
        const float xx = -rw * 0.5f + ((float)px + ((float)gx + 0.5f) * 0.5f) * bin_w;

        const float x = xx * ctt - yy * st + cwv;
        const float y = xx * st + yy * ctt + chv;

        const bool valid = (y > -1.0f) && (y < 256.0f) && (x > -1.0f) && (x < 256.0f);

        const float yc = fmaxf(y, 0.0f);
        const float xc = fmaxf(x, 0.0f);
        int yl = (int)yc;
        int xl = (int)xc;
        int yh, xh;
        float yv, xv;
        if (yl >= HH - 1) { yl = HH - 1; yh = HH - 1; yv = (float)(HH - 1); }
        else              { yh = yl + 1;              yv = yc; }
        if (xl >= WW - 1) { xl = WW - 1; xh = WW - 1; xv = (float)(WW - 1); }
        else              { xh = xl + 1;              xv = xc; }

        const float ly = yv - (float)yl;
        const float lx = xv - (float)xl;
        const float vm  = valid ? 1.0f : 0.0f;
        const float hyv = (1.0f - ly) * vm;
        const float lyv = ly * vm;
        const float hx  = 1.0f - lx;

        const int rowL = yl * WW;
        const int rowH = yh * WW;

        // side 0: x = xl, wx = hx ; side 1: x = xh, wx = lx
        sgeo[2 * s + 0] = make_float4(__int_as_float(rowL + xl),
                                      __int_as_float(rowH + xl),
                                      hx * hyv, hx * lyv);
        sgeo[2 * s + 1] = make_float4(__int_as_float(rowL + xh),
                                      __int_as_float(rowH + xh),
                                      lx * hyv, lx * lyv);
    }
    __syncthreads();

    // base: features[b, cg*16 + {0,1}*8 + plane, :, :]
    const float* fbase = features + ((size_t)b * CT + (size_t)cg * 16) * (size_t)HW;

    const int warp = tid >> 5;
    const int lane = tid & 31;
    const int isub = lane >> 3;          // item within warp's group of 4
    const int sub8 = lane & 7;           // (sample(2b), side(1b)) within bin

    for (int gBase = warp * 4; gBase < NITEM; gBase += 32) {
        const int g     = gBase + isub;
        const int plane = g / NBIN;
        const int j     = g - plane * NBIN;
        const int bin   = bin_perm(j);   // 2x2-grouped bin order

        const float4 gg = sgeo[bin * 8 + sub8];
        const int offL  = __float_as_int(gg.x);
        const int offH  = __float_as_int(gg.y);

        const float* p0 = fbase + plane * HW;
        const float* p1 = p0 + OO * HW;

        const float t0L = __ldg(p0 + offL);
        const float t0H = __ldg(p0 + offH);
        const float t1L = __ldg(p1 + offL);
        const float t1H = __ldg(p1 + offH);

        float v0 = gg.z * t0L + gg.w * t0H;
        float v1 = gg.z * t1L + gg.w * t1H;

        // sum the 8 lanes (4 samples x 2 sides) of this bin
        v0 += __shfl_xor_sync(0xFFFFFFFFu, v0, 1);
        v1 += __shfl_xor_sync(0xFFFFFFFFu, v1, 1);
        v0 += __shfl_xor_sync(0xFFFFFFFFu, v0, 2);
        v1 += __shfl_xor_sync(0xFFFFFFFFu, v1, 2);
        v0 += __shfl_xor_sync(0xFFFFFFFFu, v0, 4);
        v1 += __shfl_xor_sync(0xFFFFFFFFu, v1, 4);

        if (sub8 == 0) {
            const int a = plane * NBIN + bin;
            acc[a]         = v0;
            acc[NITEM + a] = v1;
        }
    }
    __syncthreads();

    // out[r, cg*16 .. +16, 7, 7]: contiguous 784 floats; j = cc*392 + o*49 + bin.
    float* ob = out + ((size_t)r * CT + (size_t)cg * 16) * (size_t)NBIN;
    #pragma unroll
    for (int jj = 0; jj < 4; ++jj) {
        const int j = jj * 256 + tid;
        if (j < NOUT) {
            const int cc   = j / NITEM;
            const int rest = j - cc * NITEM;
            const int o    = rest / NBIN;
            const int bin  = rest - o * NBIN;
            const int p0i  = (o - ind + 8) & 7;
            const int p1i  = (p0i + 1) & 7;
            ob[j] = 0.25f * (rv * acc[cc * NITEM + p0i * NBIN + bin]
                           + lv * acc[cc * NITEM + p1i * NBIN + bin]);
        }
    }
}

extern "C" void kernel_launch(void* const* d_in, const int* in_sizes, int n_in,
                              void* d_out, int out_size)
{
    const float* features = (const float*)d_in[0];
    const float* rois     = (const float*)d_in[1];
    float*       out      = (float*)d_out;

    const int R = in_sizes[1] / 6;
    dim3 grid((unsigned)R, 16);
    riroi_kernel<<<grid, 256>>>(features, rois, out);
}